// round 5
// baseline (speedup 1.0000x reference)
#include <cuda_runtime.h>
#include <cstdint>

// BsplineEncoding: x[1e6,3] -> out[1e6,195]. Per (point,dim): [x, 64 bins],
// only 4 bins nonzero, but all 195M floats must be written.
//
// R3 (117.4us): smem staging + float4 STG stream. DRAM 79.2%, L1 68%.
// R4: replace the LDS+STG drain with ONE cp.async.bulk (TMA) store per block
// — smem is read directly by the TMA engine, eliminating 2/3 of L1 traffic
// and all store instructions. Targets the residual gap to the ~6.9TB/s cap.

static constexpr float SCALE    = 30.5f;            // (K-DEG)/(MAX-MIN) = 61/2
static constexpr float CLAMP_HI = 61.0f - 1e-6f;    // K - DEG - EPS
static constexpr int   PTS_PER_BLK = 32;
static constexpr int   TILE_FLOATS = PTS_PER_BLK * 195;   // 6240
static constexpr int   TILE_BYTES  = TILE_FLOATS * 4;     // 24960 (16B multiple)
static constexpr int   TILE_VEC4   = TILE_FLOATS / 4;     // 1560
static constexpr int   THREADS     = 256;

__device__ __forceinline__ uint32_t smem_u32(const void* p) {
    uint32_t a;
    asm("{ .reg .u64 t; cvta.to.shared.u64 t, %1; cvt.u32.u64 %0, t; }"
        : "=r"(a) : "l"(p));
    return a;
}

__global__ __launch_bounds__(THREADS)
void bspline_enc_kernel(const float* __restrict__ xin,
                        float* __restrict__ out)
{
    __shared__ __align__(16) float tile[TILE_FLOATS];
    const int tid = threadIdx.x;

    // Phase 1: zero the tile with float4 stores.
    float4 z4 = make_float4(0.f, 0.f, 0.f, 0.f);
    float4* t4 = reinterpret_cast<float4*>(tile);
#pragma unroll
    for (int i = tid; i < TILE_VEC4; i += THREADS)
        t4[i] = z4;
    __syncthreads();

    // Phase 2: 96 workers, one per (point, dim). Coalesced input load.
    if (tid < PTS_PER_BLK * 3) {
        const int p = tid / 3;
        const int d = tid - p * 3;
        const float xv = __ldg(xin + (size_t)blockIdx.x * (PTS_PER_BLK * 3) + tid);

        float xs = fminf(fmaxf((xv + 1.0f) * SCALE, 0.0f), CLAMP_HI);
        float fi = floorf(xs);
        int  idx = (int)fi;
        float u  = xs - fi;
        float u2 = u * u;
        float u3 = u2 * u;
        float om = 1.0f - u;
        float c0 = om * om * om * (1.0f / 6.0f);
        float c1 = (3.0f * u3 - 6.0f * u2 + 4.0f) * (1.0f / 6.0f);
        float c2 = (-3.0f * u3 + 3.0f * u2 + 3.0f * u + 1.0f) * (1.0f / 6.0f);
        float c3 = u3 * (1.0f / 6.0f);

        float* dst = tile + p * 195 + d * 65;
        dst[0]       = xv;
        dst[1 + idx] = c0;
        dst[2 + idx] = c1;
        dst[3 + idx] = c2;
        dst[4 + idx] = c3;
    }
    __syncthreads();

    // Phase 3: one bulk-async (TMA) store: smem tile -> gmem, 24960 bytes.
    if (tid == 0) {
        // Order the generic-proxy smem writes before the async-proxy read.
        asm volatile("fence.proxy.async.shared::cta;" ::: "memory");
        float* gdst = out + (size_t)blockIdx.x * TILE_FLOATS;
        uint32_t src = smem_u32(tile);
        asm volatile(
            "cp.async.bulk.global.shared::cta.bulk_group [%0], [%1], %2;"
            :: "l"(gdst), "r"(src), "n"(TILE_BYTES)
            : "memory");
        asm volatile("cp.async.bulk.commit_group;" ::: "memory");
        // smem dies at block exit; the bulk read must finish first.
        asm volatile("cp.async.bulk.wait_group 0;" ::: "memory");
    }
}

extern "C" void kernel_launch(void* const* d_in, const int* in_sizes, int n_in,
                              void* d_out, int out_size)
{
    const float* x = (const float*)d_in[0];
    float* out = (float*)d_out;

    int n_points = out_size / 195;
    int blocks   = n_points / PTS_PER_BLK;   // 31250 for N = 1e6
    bspline_enc_kernel<<<blocks, THREADS>>>(x, out);
}

// round 7
// speedup vs baseline: 1.0264x; 1.0264x over previous
#include <cuda_runtime.h>
#include <cstdint>

// BsplineEncoding: x[1e6,3] -> out[1e6,195]. Per (point,dim): [x, 64 bins],
// only 4 bins nonzero; all 195M floats written.
//
// R3/R4 established: smem-staged streaming hits ~6.8 TB/s effective write BW
// (DRAM ~80%), path-independent (STG == TMA). R5: amortize per-block costs —
// 64 points/tile (48.75KB smem, 15625 blocks, halves barriers/launch work)
// and two back-to-back bulk-async stores for a deeper TMA queue.

static constexpr float SCALE    = 30.5f;            // (K-DEG)/(MAX-MIN) = 61/2
static constexpr float CLAMP_HI = 61.0f - 1e-6f;    // K - DEG - EPS
static constexpr int   PTS_PER_BLK = 64;
static constexpr int   TILE_FLOATS = PTS_PER_BLK * 195;   // 12480
static constexpr int   TILE_BYTES  = TILE_FLOATS * 4;     // 49920
static constexpr int   HALF_BYTES  = TILE_BYTES / 2;      // 24960 (16B multiple)
static constexpr int   HALF_FLOATS = TILE_FLOATS / 2;     // 6240
static constexpr int   TILE_VEC4   = TILE_FLOATS / 4;     // 3120
static constexpr int   THREADS     = 256;

__device__ __forceinline__ uint32_t smem_u32(const void* p) {
    uint32_t a;
    asm("{ .reg .u64 t; cvta.to.shared.u64 t, %1; cvt.u32.u64 %0, t; }"
        : "=r"(a) : "l"(p));
    return a;
}

__global__ __launch_bounds__(THREADS)
void bspline_enc_kernel(const float* __restrict__ xin,
                        float* __restrict__ out)
{
    __shared__ __align__(16) float tile[TILE_FLOATS];
    const int tid = threadIdx.x;

    // Phase 1: zero the tile (float4 stores, conflict-free).
    float4 z4 = make_float4(0.f, 0.f, 0.f, 0.f);
    float4* t4 = reinterpret_cast<float4*>(tile);
#pragma unroll
    for (int i = tid; i < TILE_VEC4; i += THREADS)
        t4[i] = z4;
    __syncthreads();

    // Phase 2: 192 workers, one per (point, dim). Coalesced input load.
    if (tid < PTS_PER_BLK * 3) {
        const int p = tid / 3;
        const int d = tid - p * 3;
        const float xv = __ldg(xin + (size_t)blockIdx.x * (PTS_PER_BLK * 3) + tid);

        float xs = fminf(fmaxf((xv + 1.0f) * SCALE, 0.0f), CLAMP_HI);
        float fi = floorf(xs);
        int  idx = (int)fi;
        float u  = xs - fi;
        float u2 = u * u;
        float u3 = u2 * u;
        float om = 1.0f - u;
        float c0 = om * om * om * (1.0f / 6.0f);
        float c1 = (3.0f * u3 - 6.0f * u2 + 4.0f) * (1.0f / 6.0f);
        float c2 = (-3.0f * u3 + 3.0f * u2 + 3.0f * u + 1.0f) * (1.0f / 6.0f);
        float c3 = u3 * (1.0f / 6.0f);

        float* dst = tile + p * 195 + d * 65;
        dst[0]       = xv;
        dst[1 + idx] = c0;
        dst[2 + idx] = c1;
        dst[3 + idx] = c2;
        dst[4 + idx] = c3;
    }
    __syncthreads();

    // Phase 3: two bulk-async (TMA) stores, queued back-to-back.
    if (tid == 0) {
        asm volatile("fence.proxy.async.shared::cta;" ::: "memory");
        float* gdst = out + (size_t)blockIdx.x * TILE_FLOATS;
        uint32_t src = smem_u32(tile);
        asm volatile(
            "cp.async.bulk.global.shared::cta.bulk_group [%0], [%1], %2;"
            :: "l"(gdst), "r"(src), "n"(HALF_BYTES) : "memory");
        asm volatile(
            "cp.async.bulk.global.shared::cta.bulk_group [%0], [%1], %2;"
            :: "l"(gdst + HALF_FLOATS), "r"(src + HALF_BYTES), "n"(HALF_BYTES)
            : "memory");
        asm volatile("cp.async.bulk.commit_group;" ::: "memory");
        // smem dies at block exit; bulk reads must finish first.
        asm volatile("cp.async.bulk.wait_group 0;" ::: "memory");
    }
}

extern "C" void kernel_launch(void* const* d_in, const int* in_sizes, int n_in,
                              void* d_out, int out_size)
{
    const float* x = (const float*)d_in[0];
    float* out = (float*)d_out;

    int n_points = out_size / 195;
    int blocks   = n_points / PTS_PER_BLK;   // 15625 for N = 1e6
    bspline_enc_kernel<<<blocks, THREADS>>>(x, out);
}